// round 12
// baseline (speedup 1.0000x reference)
#include <cuda_runtime.h>

// Heisenberg-picture closed form (validated R2-R11, rel_err ~2.7e-7):
//   theta_i = x_i + w0_i; c_i=cos, s_i=sin; C',S' = cos/sin(w1_i) (uniform)
//   E_w = sum of Pauli-string monomials (Y-strings vanish on real product states).
// R12: R7 champion shape (block 256, 1024 CTAs, ILP=4, regs<=32 full residency)
// + compile-time stride specialization (Q=262144 -> LDG/STG immediate offsets,
// no index IMADs, no hot-path guards) + loads hoisted ahead of uniform setup.

// Small-angle weight trig (w1 = 0.01*N(0,1); series exact to ~1e-9).
__device__ __forceinline__ void weight_trig(float w, float& s, float& c) {
    float w2 = w * w;
    s = w * fmaf(w2, fmaf(w2, 8.3333333e-3f, -1.6666667e-1f), 1.0f);
    c = fmaf(w2, fmaf(w2, 4.1666667e-2f, -0.5f), 1.0f);
}

struct K {
    float g0, g1, g2, g3, g4, g5, g6, g7, g8, g9;
    float g10, g11, g12, g13, g14, g15, g16, g17;
    float w0x, w0y, w0z, w0w;
};

__device__ __forceinline__ void make_coeffs(const float4* __restrict__ w, K& k) {
    float4 w0 = w[0];
    float4 w1 = w[1];
    float C[4], S[4];
    weight_trig(w1.x, S[0], C[0]);
    weight_trig(w1.y, S[1], C[1]);
    weight_trig(w1.z, S[2], C[2]);
    weight_trig(w1.w, S[3], C[3]);

    k.w0x = w0.x; k.w0y = w0.y; k.w0z = w0.z; k.w0w = w0.w;
    float c0c1 = C[0] * C[1];
    float c0s1 = C[0] * S[1];
    float s0c1 = S[0] * C[1];
    float s0s1 = S[0] * S[1];
    k.g0  =  C[0];            k.g1  = -S[0];
    k.g2  =  c0c1;            k.g3  = -c0s1;           k.g4  =  s0s1;
    k.g5  =  c0c1 * C[2];     k.g6  = -c0c1 * S[2];
    k.g7  =  c0s1 * S[2];     k.g8  = -s0c1 * C[2];    k.g9  = -s0s1 * S[2];
    k.g10 =  k.g5 * C[3];     k.g11 = -k.g5 * S[3];    k.g12 = -k.g6 * S[3];
    k.g13 = -c0s1 * C[2] * C[3];
    k.g14 = -c0s1 * S[2] * S[3];
    k.g15 = -k.g8 * S[3];
    k.g16 =  s0s1 * C[2] * C[3];
    k.g17 = -k.g9 * S[3];
}

__device__ __forceinline__ float4 eval_elem(float4 xv, const K& k) {
    float C0, S0, C1, S1, C2, S2, C3, S3;
    __sincosf(xv.x + k.w0x, &S0, &C0);
    __sincosf(xv.y + k.w0y, &S1, &C1);
    __sincosf(xv.z + k.w0z, &S2, &C2);
    __sincosf(xv.w + k.w0w, &S3, &C3);

    float s0s1 = S0 * S1;
    float s1s2 = S1 * S2;
    float s0s2 = S0 * S2;
    float s2s3 = S2 * S3;
    float c0s1 = C0 * S1;
    float c0c2 = C0 * C2;
    float s0s3 = S0 * S3;
    float s2c3 = S2 * C3;
    float c2s3 = C2 * S3;

    float e0 = fmaf(k.g0, C0, k.g1 * s0s1);

    float e1 = fmaf(k.g2, C1, fmaf(k.g3, C0 * s1s2, k.g4 * s0s2));

    float e2 = k.g5 * c0c2;
    e2 = fmaf(k.g6, C1 * s2s3, e2);
    e2 = fmaf(k.g7, c0s1 * S3, e2);
    e2 = fmaf(k.g8, s0s1 * C2, e2);
    e2 = fmaf(k.g9, s0s3, e2);

    float t1 = fmaf(k.g12, S2, k.g10 * C3);
    float t2 = fmaf(k.g13, s2c3, k.g14);
    float t3 = fmaf(k.g16, s2c3, k.g17);
    float e3 = C1 * t1;
    e3 = fmaf(c0s1, t2, e3);
    e3 = fmaf(S0, t3, e3);
    e3 = fmaf(k.g11, c0c2 * S3, e3);
    e3 = fmaf(k.g15, s0s1 * c2s3, e3);

    return make_float4(e0, e1, e2, e3);
}

// Hot kernel: n == 4*Q exactly (checked host-side). Q is a compile-time
// constant so x[tid + j*Q] folds into the LDG/STG immediate-offset field:
// one address register, zero index IMADs, zero guards.
template <int Q>
__global__ __launch_bounds__(256)
void qsim_kernel_fixed(const float4* __restrict__ x, const float4* __restrict__ w,
                       float4* __restrict__ out) {
    int tid = blockIdx.x * 256 + threadIdx.x;

    const float4* xp = x + tid;
    float4* op = out + tid;

    // Loads first: DRAM latency overlaps the uniform coefficient setup below.
    float4 x0 = xp[0];
    float4 x1 = xp[Q];
    float4 x2 = xp[2 * Q];
    float4 x3 = xp[3 * Q];

    K k;
    make_coeffs(w, k);

    float4 e0 = eval_elem(x0, k);
    float4 e1 = eval_elem(x1, k);
    float4 e2 = eval_elem(x2, k);
    float4 e3 = eval_elem(x3, k);

    op[0]     = e0;
    op[Q]     = e1;
    op[2 * Q] = e2;
    op[3 * Q] = e3;
}

// Generic fallback for any n (guards + runtime stride).
__global__ __launch_bounds__(256)
void qsim_kernel_generic(const float4* __restrict__ x, const float4* __restrict__ w,
                         float4* __restrict__ out, int q, int n) {
    int tid = blockIdx.x * 256 + threadIdx.x;
    if (tid >= q) return;

    K k;
    make_coeffs(w, k);

#pragma unroll
    for (int j = 0; j < 4; j++) {
        int i = tid + j * q;
        if (i < n) out[i] = eval_elem(x[i], k);
    }
}

extern "C" void kernel_launch(void* const* d_in, const int* in_sizes, int n_in,
                              void* d_out, int out_size) {
    const float4* x = (const float4*)d_in[0];     // [B, 4] float32
    const float4* w = (const float4*)d_in[1];     // [2, 4] float32
    float4* out = (float4*)d_out;                 // [B, 4] float32

    int n = in_sizes[0] / 4;                      // batch size

    constexpr int Q = 262144;                     // 1,048,576 / 4
    if (n == 4 * Q) {
        // Hot path for the actual dataset: 1024 CTAs, immediate offsets.
        qsim_kernel_fixed<Q><<<Q / 256, 256>>>(x, w, out);
    } else {
        int q = (n + 3) / 4;
        int grid = (q + 255) / 256;
        qsim_kernel_generic<<<grid, 256>>>(x, w, out, q, n);
    }
}

// round 13
// speedup vs baseline: 1.0295x; 1.0295x over previous
#include <cuda_runtime.h>

// Heisenberg-picture closed form (validated R2-R12, rel_err ~2.7e-7):
//   theta_i = x_i + w0_i; c_i=cos, s_i=sin; C',S' = cos/sin(w1_i) (uniform)
//   E_w = sum of Pauli-string monomials (Y-strings vanish on real product states).
// R13 (final): R7 champion shape EXACTLY (block 256, 1024 CTAs, ILP=4,
// coeffs-before-loads ordering that holds regs at 32 = full residency),
// plus compile-time stride Q so strided LDG/STG use immediate offsets
// (removes index IMADs / idx-ok bookkeeping; adds no live registers).

// Small-angle weight trig (w1 = 0.01*N(0,1); series exact to ~1e-9).
__device__ __forceinline__ void weight_trig(float w, float& s, float& c) {
    float w2 = w * w;
    s = w * fmaf(w2, fmaf(w2, 8.3333333e-3f, -1.6666667e-1f), 1.0f);
    c = fmaf(w2, fmaf(w2, 4.1666667e-2f, -0.5f), 1.0f);
}

struct K {
    float g0, g1, g2, g3, g4, g5, g6, g7, g8, g9;
    float g10, g11, g12, g13, g14, g15, g16, g17;
    float w0x, w0y, w0z, w0w;
};

__device__ __forceinline__ void make_coeffs(const float4* __restrict__ w, K& k) {
    float4 w0 = w[0];
    float4 w1 = w[1];
    float C[4], S[4];
    weight_trig(w1.x, S[0], C[0]);
    weight_trig(w1.y, S[1], C[1]);
    weight_trig(w1.z, S[2], C[2]);
    weight_trig(w1.w, S[3], C[3]);

    k.w0x = w0.x; k.w0y = w0.y; k.w0z = w0.z; k.w0w = w0.w;
    float c0c1 = C[0] * C[1];
    float c0s1 = C[0] * S[1];
    float s0c1 = S[0] * C[1];
    float s0s1 = S[0] * S[1];
    k.g0  =  C[0];            k.g1  = -S[0];
    k.g2  =  c0c1;            k.g3  = -c0s1;           k.g4  =  s0s1;
    k.g5  =  c0c1 * C[2];     k.g6  = -c0c1 * S[2];
    k.g7  =  c0s1 * S[2];     k.g8  = -s0c1 * C[2];    k.g9  = -s0s1 * S[2];
    k.g10 =  k.g5 * C[3];     k.g11 = -k.g5 * S[3];    k.g12 = -k.g6 * S[3];
    k.g13 = -c0s1 * C[2] * C[3];
    k.g14 = -c0s1 * S[2] * S[3];
    k.g15 = -k.g8 * S[3];
    k.g16 =  s0s1 * C[2] * C[3];
    k.g17 = -k.g9 * S[3];
}

__device__ __forceinline__ float4 eval_elem(float4 xv, const K& k) {
    float C0, S0, C1, S1, C2, S2, C3, S3;
    __sincosf(xv.x + k.w0x, &S0, &C0);
    __sincosf(xv.y + k.w0y, &S1, &C1);
    __sincosf(xv.z + k.w0z, &S2, &C2);
    __sincosf(xv.w + k.w0w, &S3, &C3);

    float s0s1 = S0 * S1;
    float s1s2 = S1 * S2;
    float s0s2 = S0 * S2;
    float s2s3 = S2 * S3;
    float c0s1 = C0 * S1;
    float c0c2 = C0 * C2;
    float s0s3 = S0 * S3;
    float s2c3 = S2 * C3;
    float c2s3 = C2 * S3;

    float e0 = fmaf(k.g0, C0, k.g1 * s0s1);

    float e1 = fmaf(k.g2, C1, fmaf(k.g3, C0 * s1s2, k.g4 * s0s2));

    float e2 = k.g5 * c0c2;
    e2 = fmaf(k.g6, C1 * s2s3, e2);
    e2 = fmaf(k.g7, c0s1 * S3, e2);
    e2 = fmaf(k.g8, s0s1 * C2, e2);
    e2 = fmaf(k.g9, s0s3, e2);

    float t1 = fmaf(k.g12, S2, k.g10 * C3);
    float t2 = fmaf(k.g13, s2c3, k.g14);
    float t3 = fmaf(k.g16, s2c3, k.g17);
    float e3 = C1 * t1;
    e3 = fmaf(c0s1, t2, e3);
    e3 = fmaf(S0, t3, e3);
    e3 = fmaf(k.g11, c0c2 * S3, e3);
    e3 = fmaf(k.g15, s0s1 * c2s3, e3);

    return make_float4(e0, e1, e2, e3);
}

// Hot kernel: n == 4*Q exactly (checked host-side). R7 instruction order:
// coefficient setup FIRST (keeps x-values' live ranges short, regs = 32),
// then 4 loads with compile-time immediate offsets, then 4 independent evals.
template <int Q>
__global__ __launch_bounds__(256)
void qsim_kernel_fixed(const float4* __restrict__ x, const float4* __restrict__ w,
                       float4* __restrict__ out) {
    int tid = blockIdx.x * 256 + threadIdx.x;

    K k;
    make_coeffs(w, k);

    const float4* xp = x + tid;
    float4* op = out + tid;

    // Front-batched loads (MLP=4), immediate offsets (j*Q*16B < 16MB field).
    float4 x0 = xp[0];
    float4 x1 = xp[Q];
    float4 x2 = xp[2 * Q];
    float4 x3 = xp[3 * Q];

    float4 e0 = eval_elem(x0, k);
    float4 e1 = eval_elem(x1, k);
    float4 e2 = eval_elem(x2, k);
    float4 e3 = eval_elem(x3, k);

    op[0]     = e0;
    op[Q]     = e1;
    op[2 * Q] = e2;
    op[3 * Q] = e3;
}

// Generic fallback for any n (guards + runtime stride).
__global__ __launch_bounds__(256)
void qsim_kernel_generic(const float4* __restrict__ x, const float4* __restrict__ w,
                         float4* __restrict__ out, int q, int n) {
    int tid = blockIdx.x * 256 + threadIdx.x;
    if (tid >= q) return;

    K k;
    make_coeffs(w, k);

#pragma unroll
    for (int j = 0; j < 4; j++) {
        int i = tid + j * q;
        if (i < n) out[i] = eval_elem(x[i], k);
    }
}

extern "C" void kernel_launch(void* const* d_in, const int* in_sizes, int n_in,
                              void* d_out, int out_size) {
    const float4* x = (const float4*)d_in[0];     // [B, 4] float32
    const float4* w = (const float4*)d_in[1];     // [2, 4] float32
    float4* out = (float4*)d_out;                 // [B, 4] float32

    int n = in_sizes[0] / 4;                      // batch size

    constexpr int Q = 262144;                     // 1,048,576 / 4
    if (n == 4 * Q) {
        qsim_kernel_fixed<Q><<<Q / 256, 256>>>(x, w, out);
    } else {
        int q = (n + 3) / 4;
        int grid = (q + 255) / 256;
        qsim_kernel_generic<<<grid, 256>>>(x, w, out, q, n);
    }
}